// round 7
// baseline (speedup 1.0000x reference)
#include <cuda_runtime.h>
#include <cuda_fp16.h>
#include <cstdint>

// Problem dims (fixed by the dataset)
#define BB 4
#define TT 256
#define UU 128
#define HH 512
#define VV 1024
#define MM (BB * TT * UU)   // 131072

// ---------------- scratch (module-load allocated) ----------------
__device__ float g_e[BB * TT * HH];                    // 2 MB
__device__ float g_d[BB * UU * HH];                    // 1 MB
// A fp16 fragments: [fm (8192)][fk (32)][lane (32)] x 16B  (134 MB)
__device__ uint4 g_Af[(size_t)(MM / 16) * (HH / 16) * 32];
// B fp16 fragments: [fn (128)][fk (32)][lane (32)] x 8B    (1 MB)
__device__ uint2 g_Bf[(VV / 8) * (HH / 16) * 32];

// ---------------- helpers ----------------
__device__ __forceinline__ float tanh_apx(float x) {
    float y;
    asm("tanh.approx.f32 %0, %1;" : "=f"(y) : "f"(x));
    return y;
}
// pack {lower = a, upper = b} as f16x2
__device__ __forceinline__ uint32_t cvt_f16x2(float a_low, float b_high) {
    uint32_t r;
    asm("cvt.rn.f16x2.f32 %0, %1, %2;" : "=r"(r) : "f"(b_high), "f"(a_low));
    return r;
}
// unpack f16x2 -> (float lo, float hi)
__device__ __forceinline__ float2 h2_to_f2(uint32_t h) {
    float2 f;
    asm("{ .reg .f16 lo, hi;\n\t"
        "mov.b32 {lo, hi}, %2;\n\t"
        "cvt.f32.f16 %0, lo;\n\t"
        "cvt.f32.f16 %1, hi; }"
        : "=f"(f.x), "=f"(f.y) : "r"(h));
    return f;
}
__device__ __forceinline__ unsigned long long ffma2(unsigned long long a,
                                                    unsigned long long b,
                                                    unsigned long long c) {
    unsigned long long d;
    asm("fma.rn.f32x2 %0, %1, %2, %3;" : "=l"(d) : "l"(a), "l"(b), "l"(c));
    return d;
}
__device__ __forceinline__ unsigned long long pack2(float lo, float hi) {
    unsigned long long r;
    asm("mov.b64 %0, {%1, %2};" : "=l"(r) : "f"(lo), "f"(hi));
    return r;
}
__device__ __forceinline__ float2 unpack2(unsigned long long v) {
    float2 r;
    asm("mov.b64 {%0, %1}, %2;" : "=f"(r.x), "=f"(r.y) : "l"(v));
    return r;
}
// m16n8k16 row.col fp16 -> fp16 accumulate (baseline PTX, sm_80+)
__device__ __forceinline__ void mma16816_h(uint32_t* c, const uint32_t* a,
                                           const uint32_t* b) {
    asm volatile(
        "mma.sync.aligned.m16n8k16.row.col.f16.f16.f16.f16 "
        "{%0,%1}, {%2,%3,%4,%5}, {%6,%7}, {%0,%1};"
        : "+r"(c[0]), "+r"(c[1])
        : "r"(a[0]), "r"(a[1]), "r"(a[2]), "r"(a[3]), "r"(b[0]), "r"(b[1]));
}

// ---------------- small fp32 SGEMM (projections, proven) ----------------
__global__ __launch_bounds__(256, 2) void sgemm_bias(
    const float* __restrict__ A, const float* __restrict__ W,
    const float* __restrict__ bias, float* __restrict__ C,
    int M, int N, int K)
{
    __shared__ float As[16][132];
    __shared__ float Bs[16][132];

    const int t = threadIdx.x;
    const int nBase = blockIdx.x * 128;
    const int mBase = blockIdx.y * 128;
    const int m0 = (t >> 4) * 4;
    const int n0 = (t & 15) * 4;
    const int lrow = t >> 2;
    const int lcol = (t & 3) * 4;

    unsigned long long acc[8][4];
#pragma unroll
    for (int i = 0; i < 8; i++)
#pragma unroll
        for (int jj = 0; jj < 4; jj++) acc[i][jj] = 0ULL;

    const float* Aptr0 = A + (size_t)(mBase + lrow) * K + lcol;
    const float* Aptr1 = A + (size_t)(mBase + lrow + 64) * K + lcol;
    const float* Wptr0 = W + (size_t)(nBase + lrow) * K + lcol;
    const float* Wptr1 = W + (size_t)(nBase + lrow + 64) * K + lcol;

    for (int k0 = 0; k0 < K; k0 += 16) {
        float4 a0 = *(const float4*)(Aptr0 + k0);
        float4 a1 = *(const float4*)(Aptr1 + k0);
        float4 b0 = *(const float4*)(Wptr0 + k0);
        float4 b1 = *(const float4*)(Wptr1 + k0);
        __syncthreads();
        As[lcol + 0][lrow] = a0.x; As[lcol + 1][lrow] = a0.y;
        As[lcol + 2][lrow] = a0.z; As[lcol + 3][lrow] = a0.w;
        As[lcol + 0][lrow + 64] = a1.x; As[lcol + 1][lrow + 64] = a1.y;
        As[lcol + 2][lrow + 64] = a1.z; As[lcol + 3][lrow + 64] = a1.w;
        Bs[lcol + 0][lrow] = b0.x; Bs[lcol + 1][lrow] = b0.y;
        Bs[lcol + 2][lrow] = b0.z; Bs[lcol + 3][lrow] = b0.w;
        Bs[lcol + 0][lrow + 64] = b1.x; Bs[lcol + 1][lrow + 64] = b1.y;
        Bs[lcol + 2][lrow + 64] = b1.z; Bs[lcol + 3][lrow + 64] = b1.w;
        __syncthreads();

#pragma unroll
        for (int k = 0; k < 16; k++) {
            float4 av0 = *(const float4*)&As[k][m0];
            float4 av1 = *(const float4*)&As[k][m0 + 64];
            float4 bv0 = *(const float4*)&Bs[k][n0];
            float4 bv1 = *(const float4*)&Bs[k][n0 + 64];
            unsigned long long bp[4];
            bp[0] = pack2(bv0.x, bv0.y);
            bp[1] = pack2(bv0.z, bv0.w);
            bp[2] = pack2(bv1.x, bv1.y);
            bp[3] = pack2(bv1.z, bv1.w);
            float am[8] = {av0.x, av0.y, av0.z, av0.w,
                           av1.x, av1.y, av1.z, av1.w};
#pragma unroll
            for (int i = 0; i < 8; i++) {
                unsigned long long ad = pack2(am[i], am[i]);
#pragma unroll
                for (int jj = 0; jj < 4; jj++)
                    acc[i][jj] = ffma2(ad, bp[jj], acc[i][jj]);
            }
        }
    }

    float4 bias0 = *(const float4*)(bias + nBase + n0);
    float4 bias1 = *(const float4*)(bias + nBase + n0 + 64);
#pragma unroll
    for (int i = 0; i < 8; i++) {
        const int mg = mBase + m0 + ((i < 4) ? i : (i + 60));
        float2 p0 = unpack2(acc[i][0]);
        float2 p1 = unpack2(acc[i][1]);
        float2 p2 = unpack2(acc[i][2]);
        float2 p3 = unpack2(acc[i][3]);
        float4 o0 = make_float4(p0.x + bias0.x, p0.y + bias0.y,
                                p1.x + bias0.z, p1.y + bias0.w);
        float4 o1 = make_float4(p2.x + bias1.x, p2.y + bias1.y,
                                p3.x + bias1.z, p3.y + bias1.w);
        float* crow = C + (size_t)mg * N + nBase;
        *(float4*)(crow + n0) = o0;
        *(float4*)(crow + n0 + 64) = o1;
    }
}

// ---------------- pack W -> fp16 B-fragments (m16n8k16 col) ----------------
__global__ __launch_bounds__(256) void pack_b(
    const float* __restrict__ W, uint2* __restrict__ Bf)
{
    const int gid = blockIdx.x * 256 + threadIdx.x;  // < 131072
    const int lane = gid & 31;
    const int fk = (gid >> 5) & 31;
    const int fn = gid >> 10;

    const int n = fn * 8 + (lane >> 2);
    const int k0 = fk * 16 + (lane & 3) * 2;
    const float* wr = W + (size_t)n * HH;
    float2 w01 = *(const float2*)(wr + k0);
    float2 w89 = *(const float2*)(wr + k0 + 8);

    Bf[gid] = make_uint2(cvt_f16x2(w01.x, w01.y), cvt_f16x2(w89.x, w89.y));
}

// ---------------- pack A = tanh(e (+) d) -> fp16 A-fragments ----------------
__global__ __launch_bounds__(256) void pack_a(
    const float* __restrict__ e, const float* __restrict__ dmat,
    uint4* __restrict__ Af)
{
    const int gid = blockIdx.x * 256 + threadIdx.x;  // < 8388608
    const int lane = gid & 31;
    const int fk = (gid >> 5) & 31;
    const int fm = gid >> 10;                         // < 8192

    const int g = lane >> 2;
    const int k0 = fk * 16 + (lane & 3) * 2;
    const int m0 = fm * 16 + g;
    const int bt = m0 >> 7;
    const int u0 = m0 & 127;
    const int b = bt >> 8;

    const float* erow = e + (size_t)bt * HH;
    const float* dr0 = dmat + (size_t)(b * 128 + u0) * HH;
    const float* dr1 = dr0 + 8 * HH;

    float2 e01 = *(const float2*)(erow + k0);
    float2 e89 = *(const float2*)(erow + k0 + 8);
    float2 d001 = *(const float2*)(dr0 + k0);
    float2 d089 = *(const float2*)(dr0 + k0 + 8);
    float2 d101 = *(const float2*)(dr1 + k0);
    float2 d189 = *(const float2*)(dr1 + k0 + 8);

    float x0 = tanh_apx(e01.x + d001.x), x1 = tanh_apx(e01.y + d001.y);
    float x8 = tanh_apx(e89.x + d089.x), x9 = tanh_apx(e89.y + d089.y);
    float y0 = tanh_apx(e01.x + d101.x), y1 = tanh_apx(e01.y + d101.y);
    float y8 = tanh_apx(e89.x + d189.x), y9 = tanh_apx(e89.y + d189.y);

    Af[gid] = make_uint4(cvt_f16x2(x0, x1), cvt_f16x2(y0, y1),
                         cvt_f16x2(x8, x9), cvt_f16x2(y8, y9));
}

// ---------------- joint GEMM: fp16-acc HMMA, K=64 chunked f32 promotion ----
// CTA 128x128, 8 warps as 2(M) x 4(N); warp tile 64x32.
__global__ __launch_bounds__(256) void joint_gemm(
    const uint4* __restrict__ Af, const uint2* __restrict__ Bf,
    const float* __restrict__ bias, float* __restrict__ out)
{
    const int tid = threadIdx.x;
    const int lane = tid & 31;
    const int wid = tid >> 5;
    const int wr = wid >> 2;            // 0..1  (64-row block)
    const int wc = wid & 3;             // 0..3  (32-col block)
    const int mt = blockIdx.y;          // 0..1023
    const int nt = blockIdx.x;          // 0..7

    const int fmBase = mt * 8 + wr * 4;
    const int fnBase = nt * 16 + wc * 4;

    float c[4][4][4];
#pragma unroll
    for (int i = 0; i < 4; i++)
#pragma unroll
        for (int j = 0; j < 4; j++)
#pragma unroll
            for (int q = 0; q < 4; q++) c[i][j][q] = 0.f;

    const uint4* pa[4];
    const uint2* pb[4];
#pragma unroll
    for (int i = 0; i < 4; i++)
        pa[i] = Af + ((size_t)(fmBase + i) * 32) * 32 + lane;
#pragma unroll
    for (int j = 0; j < 4; j++)
        pb[j] = Bf + ((size_t)(fnBase + j) * 32) * 32 + lane;

    for (int chunk = 0; chunk < 8; chunk++) {
        uint32_t hc[4][4][2];
#pragma unroll
        for (int i = 0; i < 4; i++)
#pragma unroll
            for (int j = 0; j < 4; j++) { hc[i][j][0] = 0u; hc[i][j][1] = 0u; }

#pragma unroll
        for (int q = 0; q < 4; q++) {
            uint4 a[4];
            uint2 b[4];
#pragma unroll
            for (int i = 0; i < 4; i++) { a[i] = __ldg(pa[i]); pa[i] += 32; }
#pragma unroll
            for (int j = 0; j < 4; j++) { b[j] = __ldg(pb[j]); pb[j] += 32; }
#pragma unroll
            for (int i = 0; i < 4; i++)
#pragma unroll
                for (int j = 0; j < 4; j++)
                    mma16816_h(hc[i][j], (const uint32_t*)&a[i],
                               (const uint32_t*)&b[j]);
        }
        // promote fp16 chunk sums into fp32 accumulators
#pragma unroll
        for (int i = 0; i < 4; i++)
#pragma unroll
            for (int j = 0; j < 4; j++) {
                float2 lo = h2_to_f2(hc[i][j][0]);
                float2 hi = h2_to_f2(hc[i][j][1]);
                c[i][j][0] += lo.x;
                c[i][j][1] += lo.y;
                c[i][j][2] += hi.x;
                c[i][j][3] += hi.y;
            }
    }

    // epilogue: C frag lane mapping: rows g, g+8 ; cols 2t, 2t+1
    const int g = lane >> 2;
    const int t2 = (lane & 3) * 2;
#pragma unroll
    for (int j = 0; j < 4; j++) {
        const int col = nt * 128 + wc * 32 + j * 8 + t2;
        const float2 bv = *(const float2*)(bias + col);
#pragma unroll
        for (int i = 0; i < 4; i++) {
            const int row = mt * 128 + wr * 64 + i * 16 + g;
            float2 o0 = make_float2(c[i][j][0] + bv.x, c[i][j][1] + bv.y);
            float2 o1 = make_float2(c[i][j][2] + bv.x, c[i][j][3] + bv.y);
            *(float2*)(out + (size_t)row * VV + col) = o0;
            *(float2*)(out + (size_t)(row + 8) * VV + col) = o1;
        }
    }
}

// ---------------- launch ----------------
extern "C" void kernel_launch(void* const* d_in, const int* in_sizes, int n_in,
                              void* d_out, int out_size)
{
    const float* enc     = (const float*)d_in[0];
    const float* dec     = (const float*)d_in[1];
    const float* W_enc   = (const float*)d_in[2];
    const float* b_enc   = (const float*)d_in[3];
    const float* W_dec   = (const float*)d_in[4];
    const float* b_dec   = (const float*)d_in[5];
    const float* W_joint = (const float*)d_in[6];
    const float* b_joint = (const float*)d_in[7];
    float* out = (float*)d_out;

    float *e_ptr, *d_ptr;
    uint4 *af;
    uint2 *bf;
    cudaGetSymbolAddress((void**)&e_ptr, g_e);
    cudaGetSymbolAddress((void**)&d_ptr, g_d);
    cudaGetSymbolAddress((void**)&af, g_Af);
    cudaGetSymbolAddress((void**)&bf, g_Bf);

    // W_joint -> fp16 fragment-ordered
    pack_b<<<(VV / 8) * (HH / 16) * 32 / 256, 256>>>(W_joint, bf);
    // projections (fp32)
    sgemm_bias<<<dim3(4, 8), 256>>>(enc, W_enc, b_enc, e_ptr, BB * TT, HH, HH);
    sgemm_bias<<<dim3(4, 4), 256>>>(dec, W_dec, b_dec, d_ptr, BB * UU, HH, HH);
    // A = tanh(e (+) d) -> fp16 fragment-ordered
    pack_a<<<(MM / 16) * (HH / 16) * 32 / 256, 256>>>(e_ptr, d_ptr, af);
    // out = A @ W^T + bias (fp16-acc HMMA, chunked promotion)
    joint_gemm<<<dim3(VV / 128, MM / 128), 256>>>(af, bf, b_joint, out);
}

// round 8
// speedup vs baseline: 1.8264x; 1.8264x over previous
#include <cuda_runtime.h>
#include <cuda_fp16.h>
#include <cstdint>

// Problem dims (fixed by the dataset)
#define BB 4
#define TT 256
#define UU 128
#define HH 512
#define VV 1024
#define MM (BB * TT * UU)   // 131072

// ---------------- scratch (module-load allocated) ----------------
__device__ float g_e[BB * TT * HH];                    // 2 MB
__device__ float g_d[BB * UU * HH];                    // 1 MB
// A fp16 fragments: [fm (8192)][fk (32)][lane (32)] x 16B  (134 MB)
__device__ uint4 g_Af[(size_t)(MM / 16) * (HH / 16) * 32];
// B fp16 fragments: [fn (128)][fk (32)][lane (32)] x 8B    (1 MB)
__device__ uint2 g_Bf[(VV / 8) * (HH / 16) * 32];

// ---------------- helpers ----------------
__device__ __forceinline__ float tanh_apx(float x) {
    float y;
    asm("tanh.approx.f32 %0, %1;" : "=f"(y) : "f"(x));
    return y;
}
// pack {lower = a, upper = b} as f16x2
__device__ __forceinline__ uint32_t cvt_f16x2(float a_low, float b_high) {
    uint32_t r;
    asm("cvt.rn.f16x2.f32 %0, %1, %2;" : "=r"(r) : "f"(b_high), "f"(a_low));
    return r;
}
__device__ __forceinline__ unsigned long long ffma2(unsigned long long a,
                                                    unsigned long long b,
                                                    unsigned long long c) {
    unsigned long long d;
    asm("fma.rn.f32x2 %0, %1, %2, %3;" : "=l"(d) : "l"(a), "l"(b), "l"(c));
    return d;
}
__device__ __forceinline__ unsigned long long pack2(float lo, float hi) {
    unsigned long long r;
    asm("mov.b64 %0, {%1, %2};" : "=l"(r) : "f"(lo), "f"(hi));
    return r;
}
__device__ __forceinline__ float2 unpack2(unsigned long long v) {
    float2 r;
    asm("mov.b64 {%0, %1}, %2;" : "=f"(r.x), "=f"(r.y) : "l"(v));
    return r;
}
// m16n8k16 row.col fp16 -> f32 accumulate (baseline PTX, sm_80+)
__device__ __forceinline__ void mma16816(float* c, const uint32_t* a,
                                         const uint32_t* b) {
    asm volatile(
        "mma.sync.aligned.m16n8k16.row.col.f32.f16.f16.f32 "
        "{%0,%1,%2,%3}, {%4,%5,%6,%7}, {%8,%9}, {%0,%1,%2,%3};"
        : "+f"(c[0]), "+f"(c[1]), "+f"(c[2]), "+f"(c[3])
        : "r"(a[0]), "r"(a[1]), "r"(a[2]), "r"(a[3]), "r"(b[0]), "r"(b[1]));
}

// ---------------- small fp32 SGEMM (projections, proven) ----------------
__global__ __launch_bounds__(256, 2) void sgemm_bias(
    const float* __restrict__ A, const float* __restrict__ W,
    const float* __restrict__ bias, float* __restrict__ C,
    int M, int N, int K)
{
    __shared__ float As[16][132];
    __shared__ float Bs[16][132];

    const int t = threadIdx.x;
    const int nBase = blockIdx.x * 128;
    const int mBase = blockIdx.y * 128;
    const int m0 = (t >> 4) * 4;
    const int n0 = (t & 15) * 4;
    const int lrow = t >> 2;
    const int lcol = (t & 3) * 4;

    unsigned long long acc[8][4];
#pragma unroll
    for (int i = 0; i < 8; i++)
#pragma unroll
        for (int jj = 0; jj < 4; jj++) acc[i][jj] = 0ULL;

    const float* Aptr0 = A + (size_t)(mBase + lrow) * K + lcol;
    const float* Aptr1 = A + (size_t)(mBase + lrow + 64) * K + lcol;
    const float* Wptr0 = W + (size_t)(nBase + lrow) * K + lcol;
    const float* Wptr1 = W + (size_t)(nBase + lrow + 64) * K + lcol;

    for (int k0 = 0; k0 < K; k0 += 16) {
        float4 a0 = *(const float4*)(Aptr0 + k0);
        float4 a1 = *(const float4*)(Aptr1 + k0);
        float4 b0 = *(const float4*)(Wptr0 + k0);
        float4 b1 = *(const float4*)(Wptr1 + k0);
        __syncthreads();
        As[lcol + 0][lrow] = a0.x; As[lcol + 1][lrow] = a0.y;
        As[lcol + 2][lrow] = a0.z; As[lcol + 3][lrow] = a0.w;
        As[lcol + 0][lrow + 64] = a1.x; As[lcol + 1][lrow + 64] = a1.y;
        As[lcol + 2][lrow + 64] = a1.z; As[lcol + 3][lrow + 64] = a1.w;
        Bs[lcol + 0][lrow] = b0.x; Bs[lcol + 1][lrow] = b0.y;
        Bs[lcol + 2][lrow] = b0.z; Bs[lcol + 3][lrow] = b0.w;
        Bs[lcol + 0][lrow + 64] = b1.x; Bs[lcol + 1][lrow + 64] = b1.y;
        Bs[lcol + 2][lrow + 64] = b1.z; Bs[lcol + 3][lrow + 64] = b1.w;
        __syncthreads();

#pragma unroll
        for (int k = 0; k < 16; k++) {
            float4 av0 = *(const float4*)&As[k][m0];
            float4 av1 = *(const float4*)&As[k][m0 + 64];
            float4 bv0 = *(const float4*)&Bs[k][n0];
            float4 bv1 = *(const float4*)&Bs[k][n0 + 64];
            unsigned long long bp[4];
            bp[0] = pack2(bv0.x, bv0.y);
            bp[1] = pack2(bv0.z, bv0.w);
            bp[2] = pack2(bv1.x, bv1.y);
            bp[3] = pack2(bv1.z, bv1.w);
            float am[8] = {av0.x, av0.y, av0.z, av0.w,
                           av1.x, av1.y, av1.z, av1.w};
#pragma unroll
            for (int i = 0; i < 8; i++) {
                unsigned long long ad = pack2(am[i], am[i]);
#pragma unroll
                for (int jj = 0; jj < 4; jj++)
                    acc[i][jj] = ffma2(ad, bp[jj], acc[i][jj]);
            }
        }
    }

    float4 bias0 = *(const float4*)(bias + nBase + n0);
    float4 bias1 = *(const float4*)(bias + nBase + n0 + 64);
#pragma unroll
    for (int i = 0; i < 8; i++) {
        const int mg = mBase + m0 + ((i < 4) ? i : (i + 60));
        float2 p0 = unpack2(acc[i][0]);
        float2 p1 = unpack2(acc[i][1]);
        float2 p2 = unpack2(acc[i][2]);
        float2 p3 = unpack2(acc[i][3]);
        float4 o0 = make_float4(p0.x + bias0.x, p0.y + bias0.y,
                                p1.x + bias0.z, p1.y + bias0.w);
        float4 o1 = make_float4(p2.x + bias1.x, p2.y + bias1.y,
                                p3.x + bias1.z, p3.y + bias1.w);
        float* crow = C + (size_t)mg * N + nBase;
        *(float4*)(crow + n0) = o0;
        *(float4*)(crow + n0 + 64) = o1;
    }
}

// ---------------- pack W -> fp16 B-fragments (m16n8k16 col) ----------------
__global__ __launch_bounds__(256) void pack_b(
    const float* __restrict__ W, uint2* __restrict__ Bf)
{
    const int gid = blockIdx.x * 256 + threadIdx.x;  // < 131072
    const int lane = gid & 31;
    const int fk = (gid >> 5) & 31;
    const int fn = gid >> 10;

    const int n = fn * 8 + (lane >> 2);
    const int k0 = fk * 16 + (lane & 3) * 2;
    const float* wr = W + (size_t)n * HH;
    float2 w01 = *(const float2*)(wr + k0);
    float2 w89 = *(const float2*)(wr + k0 + 8);

    Bf[gid] = make_uint2(cvt_f16x2(w01.x, w01.y), cvt_f16x2(w89.x, w89.y));
}

// ---------------- pack A = tanh(e (+) d) -> fp16 A-fragments ----------------
__global__ __launch_bounds__(256) void pack_a(
    const float* __restrict__ e, const float* __restrict__ dmat,
    uint4* __restrict__ Af, int gidOff)
{
    const int gid = blockIdx.x * 256 + threadIdx.x + gidOff;
    const int lane = gid & 31;
    const int fk = (gid >> 5) & 31;
    const int fm = gid >> 10;

    const int g = lane >> 2;
    const int k0 = fk * 16 + (lane & 3) * 2;
    const int m0 = fm * 16 + g;
    const int bt = m0 >> 7;
    const int u0 = m0 & 127;
    const int b = bt >> 8;

    const float* erow = e + (size_t)bt * HH;
    const float* dr0 = dmat + (size_t)(b * 128 + u0) * HH;
    const float* dr1 = dr0 + 8 * HH;

    float2 e01 = *(const float2*)(erow + k0);
    float2 e89 = *(const float2*)(erow + k0 + 8);
    float2 d001 = *(const float2*)(dr0 + k0);
    float2 d089 = *(const float2*)(dr0 + k0 + 8);
    float2 d101 = *(const float2*)(dr1 + k0);
    float2 d189 = *(const float2*)(dr1 + k0 + 8);

    float x0 = tanh_apx(e01.x + d001.x), x1 = tanh_apx(e01.y + d001.y);
    float x8 = tanh_apx(e89.x + d089.x), x9 = tanh_apx(e89.y + d089.y);
    float y0 = tanh_apx(e01.x + d101.x), y1 = tanh_apx(e01.y + d101.y);
    float y8 = tanh_apx(e89.x + d189.x), y9 = tanh_apx(e89.y + d189.y);

    Af[gid] = make_uint4(cvt_f16x2(x0, x1), cvt_f16x2(y0, y1),
                         cvt_f16x2(x8, x9), cvt_f16x2(y8, y9));
}

// ---------------- joint GEMM: out = A @ W^T + bias, single-pass HMMA ------
// CTA 128x128, 8 warps as 2(M) x 4(N); warp tile 64x32.
__global__ __launch_bounds__(256, 2) void joint_gemm(
    const uint4* __restrict__ Af, const uint2* __restrict__ Bf,
    const float* __restrict__ bias, float* __restrict__ out, int mtOff)
{
    const int tid = threadIdx.x;
    const int lane = tid & 31;
    const int wid = tid >> 5;
    const int wr = wid >> 2;            // 0..1  (64-row block)
    const int wc = wid & 3;             // 0..3  (32-col block)
    const int mt = blockIdx.y + mtOff;  // 0..1023
    const int nt = blockIdx.x;          // 0..7

    const int fmBase = mt * 8 + wr * 4;
    const int fnBase = nt * 16 + wc * 4;

    float c[4][4][4];
#pragma unroll
    for (int i = 0; i < 4; i++)
#pragma unroll
        for (int j = 0; j < 4; j++)
#pragma unroll
            for (int q = 0; q < 4; q++) c[i][j][q] = 0.f;

    const uint4* pa[4];
    const uint2* pb[4];
#pragma unroll
    for (int i = 0; i < 4; i++)
        pa[i] = Af + ((size_t)(fmBase + i) * 32) * 32 + lane;
#pragma unroll
    for (int j = 0; j < 4; j++)
        pb[j] = Bf + ((size_t)(fnBase + j) * 32) * 32 + lane;

    for (int fk = 0; fk < 32; fk++) {
        uint4 a[4];
        uint2 b[4];
#pragma unroll
        for (int i = 0; i < 4; i++) { a[i] = __ldg(pa[i]); pa[i] += 32; }
#pragma unroll
        for (int j = 0; j < 4; j++) { b[j] = __ldg(pb[j]); pb[j] += 32; }
#pragma unroll
        for (int i = 0; i < 4; i++)
#pragma unroll
            for (int j = 0; j < 4; j++)
                mma16816(c[i][j], (const uint32_t*)&a[i], (const uint32_t*)&b[j]);
    }

    // epilogue: C frag lane mapping: rows g, g+8 ; cols 2t, 2t+1
    const int g = lane >> 2;
    const int t2 = (lane & 3) * 2;
#pragma unroll
    for (int j = 0; j < 4; j++) {
        const int col = nt * 128 + wc * 32 + j * 8 + t2;
        const float2 bv = *(const float2*)(bias + col);
#pragma unroll
        for (int i = 0; i < 4; i++) {
            const int row = mt * 128 + wr * 64 + i * 16 + g;
            float2 o0 = make_float2(c[i][j][0] + bv.x, c[i][j][1] + bv.y);
            float2 o1 = make_float2(c[i][j][2] + bv.x, c[i][j][3] + bv.y);
            *(float2*)(out + (size_t)row * VV + col) = o0;
            *(float2*)(out + (size_t)(row + 8) * VV + col) = o1;
        }
    }
}

// ---------------- launch (two-stream fork/join, graph-capturable) ----------
extern "C" void kernel_launch(void* const* d_in, const int* in_sizes, int n_in,
                              void* d_out, int out_size)
{
    const float* enc     = (const float*)d_in[0];
    const float* dec     = (const float*)d_in[1];
    const float* W_enc   = (const float*)d_in[2];
    const float* b_enc   = (const float*)d_in[3];
    const float* W_dec   = (const float*)d_in[4];
    const float* b_dec   = (const float*)d_in[5];
    const float* W_joint = (const float*)d_in[6];
    const float* b_joint = (const float*)d_in[7];
    float* out = (float*)d_out;

    float *e_ptr, *d_ptr;
    uint4 *af;
    uint2 *bf;
    cudaGetSymbolAddress((void**)&e_ptr, g_e);
    cudaGetSymbolAddress((void**)&d_ptr, g_d);
    cudaGetSymbolAddress((void**)&af, g_Af);
    cudaGetSymbolAddress((void**)&bf, g_Bf);

    static cudaStream_t s2 = nullptr;
    static cudaEvent_t evF = nullptr, evD = nullptr, evE = nullptr, evEnd = nullptr;
    if (s2 == nullptr) {
        cudaStreamCreateWithFlags(&s2, cudaStreamNonBlocking);
        cudaEventCreateWithFlags(&evF, cudaEventDisableTiming);
        cudaEventCreateWithFlags(&evD, cudaEventDisableTiming);
        cudaEventCreateWithFlags(&evE, cudaEventDisableTiming);
        cudaEventCreateWithFlags(&evEnd, cudaEventDisableTiming);
    }

    const int HALF_GID = (MM / 16) * (HH / 16) * 32 / 2;  // 4194304

    // fork: s2 branches off the capture stream
    cudaEventRecord(evF, 0);
    cudaStreamWaitEvent(s2, evF, 0);

    // s2: pack_b ; proj_d
    pack_b<<<(VV / 8) * (HH / 16) * 32 / 256, 256, 0, s2>>>(W_joint, bf);
    sgemm_bias<<<dim3(4, 4), 256, 0, s2>>>(dec, W_dec, b_dec, d_ptr,
                                           BB * UU, HH, HH);
    cudaEventRecord(evD, s2);

    // s0: proj_e
    sgemm_bias<<<dim3(4, 8), 256>>>(enc, W_enc, b_enc, e_ptr, BB * TT, HH, HH);
    cudaEventRecord(evE, 0);

    // s0: needs d too -> wait evD, then pack_a half 0, gemm half 0
    cudaStreamWaitEvent(0, evD, 0);
    pack_a<<<HALF_GID / 256, 256>>>(e_ptr, d_ptr, af, 0);
    joint_gemm<<<dim3(VV / 128, MM / 256), 256>>>(af, bf, b_joint, out, 0);

    // s2: needs e -> wait evE, then pack_a half 1, gemm half 1
    cudaStreamWaitEvent(s2, evE, 0);
    pack_a<<<HALF_GID / 256, 256, 0, s2>>>(e_ptr, d_ptr, af, HALF_GID);
    joint_gemm<<<dim3(VV / 128, MM / 256), 256, 0, s2>>>(af, bf, b_joint, out,
                                                         MM / 256);
    cudaEventRecord(evEnd, s2);

    // join back into the capture stream
    cudaStreamWaitEvent(0, evEnd, 0);
}

// round 10
// speedup vs baseline: 1.8393x; 1.0071x over previous
#include <cuda_runtime.h>
#include <cuda_fp16.h>
#include <cstdint>

// Problem dims (fixed by the dataset)
#define BB 4
#define TT 256
#define UU 128
#define HH 512
#define VV 1024
#define MM (BB * TT * UU)   // 131072

// ---------------- scratch (module-load allocated) ----------------
__device__ float g_e[BB * TT * HH];                    // 2 MB
__device__ float g_d[BB * UU * HH];                    // 1 MB
// A fp16 fragments: [fm (8192)][fk (32)][lane (32)] x 16B  (134 MB)
__device__ uint4 g_Af[(size_t)(MM / 16) * (HH / 16) * 32];
// B fp16 fragments: [fn (128)][fk (32)][lane (32)] x 8B    (1 MB)
__device__ uint2 g_Bf[(VV / 8) * (HH / 16) * 32];

// ---------------- helpers ----------------
__device__ __forceinline__ float tanh_apx(float x) {
    float y;
    asm("tanh.approx.f32 %0, %1;" : "=f"(y) : "f"(x));
    return y;
}
// pack {lower = a, upper = b} as f16x2
__device__ __forceinline__ uint32_t cvt_f16x2(float a_low, float b_high) {
    uint32_t r;
    asm("cvt.rn.f16x2.f32 %0, %1, %2;" : "=r"(r) : "f"(b_high), "f"(a_low));
    return r;
}
__device__ __forceinline__ unsigned long long ffma2(unsigned long long a,
                                                    unsigned long long b,
                                                    unsigned long long c) {
    unsigned long long d;
    asm("fma.rn.f32x2 %0, %1, %2, %3;" : "=l"(d) : "l"(a), "l"(b), "l"(c));
    return d;
}
__device__ __forceinline__ unsigned long long pack2(float lo, float hi) {
    unsigned long long r;
    asm("mov.b64 %0, {%1, %2};" : "=l"(r) : "f"(lo), "f"(hi));
    return r;
}
__device__ __forceinline__ float2 unpack2(unsigned long long v) {
    float2 r;
    asm("mov.b64 {%0, %1}, %2;" : "=f"(r.x), "=f"(r.y) : "l"(v));
    return r;
}
// m16n8k16 row.col fp16 -> f32 accumulate (baseline PTX, sm_80+)
__device__ __forceinline__ void mma16816(float* c, const uint32_t* a,
                                         const uint32_t* b) {
    asm volatile(
        "mma.sync.aligned.m16n8k16.row.col.f32.f16.f16.f32 "
        "{%0,%1,%2,%3}, {%4,%5,%6,%7}, {%8,%9}, {%0,%1,%2,%3};"
        : "+f"(c[0]), "+f"(c[1]), "+f"(c[2]), "+f"(c[3])
        : "r"(a[0]), "r"(a[1]), "r"(a[2]), "r"(a[3]), "r"(b[0]), "r"(b[1]));
}

// ---------------- small fp32 SGEMM (projections, proven) ----------------
__global__ __launch_bounds__(256, 2) void sgemm_bias(
    const float* __restrict__ A, const float* __restrict__ W,
    const float* __restrict__ bias, float* __restrict__ C,
    int M, int N, int K)
{
    __shared__ float As[16][132];
    __shared__ float Bs[16][132];

    const int t = threadIdx.x;
    const int nBase = blockIdx.x * 128;
    const int mBase = blockIdx.y * 128;
    const int m0 = (t >> 4) * 4;
    const int n0 = (t & 15) * 4;
    const int lrow = t >> 2;
    const int lcol = (t & 3) * 4;

    unsigned long long acc[8][4];
#pragma unroll
    for (int i = 0; i < 8; i++)
#pragma unroll
        for (int jj = 0; jj < 4; jj++) acc[i][jj] = 0ULL;

    const float* Aptr0 = A + (size_t)(mBase + lrow) * K + lcol;
    const float* Aptr1 = A + (size_t)(mBase + lrow + 64) * K + lcol;
    const float* Wptr0 = W + (size_t)(nBase + lrow) * K + lcol;
    const float* Wptr1 = W + (size_t)(nBase + lrow + 64) * K + lcol;

    for (int k0 = 0; k0 < K; k0 += 16) {
        float4 a0 = *(const float4*)(Aptr0 + k0);
        float4 a1 = *(const float4*)(Aptr1 + k0);
        float4 b0 = *(const float4*)(Wptr0 + k0);
        float4 b1 = *(const float4*)(Wptr1 + k0);
        __syncthreads();
        As[lcol + 0][lrow] = a0.x; As[lcol + 1][lrow] = a0.y;
        As[lcol + 2][lrow] = a0.z; As[lcol + 3][lrow] = a0.w;
        As[lcol + 0][lrow + 64] = a1.x; As[lcol + 1][lrow + 64] = a1.y;
        As[lcol + 2][lrow + 64] = a1.z; As[lcol + 3][lrow + 64] = a1.w;
        Bs[lcol + 0][lrow] = b0.x; Bs[lcol + 1][lrow] = b0.y;
        Bs[lcol + 2][lrow] = b0.z; Bs[lcol + 3][lrow] = b0.w;
        Bs[lcol + 0][lrow + 64] = b1.x; Bs[lcol + 1][lrow + 64] = b1.y;
        Bs[lcol + 2][lrow + 64] = b1.z; Bs[lcol + 3][lrow + 64] = b1.w;
        __syncthreads();

#pragma unroll
        for (int k = 0; k < 16; k++) {
            float4 av0 = *(const float4*)&As[k][m0];
            float4 av1 = *(const float4*)&As[k][m0 + 64];
            float4 bv0 = *(const float4*)&Bs[k][n0];
            float4 bv1 = *(const float4*)&Bs[k][n0 + 64];
            unsigned long long bp[4];
            bp[0] = pack2(bv0.x, bv0.y);
            bp[1] = pack2(bv0.z, bv0.w);
            bp[2] = pack2(bv1.x, bv1.y);
            bp[3] = pack2(bv1.z, bv1.w);
            float am[8] = {av0.x, av0.y, av0.z, av0.w,
                           av1.x, av1.y, av1.z, av1.w};
#pragma unroll
            for (int i = 0; i < 8; i++) {
                unsigned long long ad = pack2(am[i], am[i]);
#pragma unroll
                for (int jj = 0; jj < 4; jj++)
                    acc[i][jj] = ffma2(ad, bp[jj], acc[i][jj]);
            }
        }
    }

    float4 bias0 = *(const float4*)(bias + nBase + n0);
    float4 bias1 = *(const float4*)(bias + nBase + n0 + 64);
#pragma unroll
    for (int i = 0; i < 8; i++) {
        const int mg = mBase + m0 + ((i < 4) ? i : (i + 60));
        float2 p0 = unpack2(acc[i][0]);
        float2 p1 = unpack2(acc[i][1]);
        float2 p2 = unpack2(acc[i][2]);
        float2 p3 = unpack2(acc[i][3]);
        float4 o0 = make_float4(p0.x + bias0.x, p0.y + bias0.y,
                                p1.x + bias0.z, p1.y + bias0.w);
        float4 o1 = make_float4(p2.x + bias1.x, p2.y + bias1.y,
                                p3.x + bias1.z, p3.y + bias1.w);
        float* crow = C + (size_t)mg * N + nBase;
        *(float4*)(crow + n0) = o0;
        *(float4*)(crow + n0 + 64) = o1;
    }
}

// ---------------- pack W -> fp16 B-fragments (m16n8k16 col) ----------------
__global__ __launch_bounds__(256) void pack_b(
    const float* __restrict__ W, uint2* __restrict__ Bf)
{
    const int gid = blockIdx.x * 256 + threadIdx.x;  // < 131072
    const int lane = gid & 31;
    const int fk = (gid >> 5) & 31;
    const int fn = gid >> 10;

    const int n = fn * 8 + (lane >> 2);
    const int k0 = fk * 16 + (lane & 3) * 2;
    const float* wr = W + (size_t)n * HH;
    float2 w01 = *(const float2*)(wr + k0);
    float2 w89 = *(const float2*)(wr + k0 + 8);

    Bf[gid] = make_uint2(cvt_f16x2(w01.x, w01.y), cvt_f16x2(w89.x, w89.y));
}

// ---------------- pack A = tanh(e (+) d) -> fp16 A-fragments ----------------
__global__ __launch_bounds__(256) void pack_a(
    const float* __restrict__ e, const float* __restrict__ dmat,
    uint4* __restrict__ Af, int gidOff)
{
    const int gid = blockIdx.x * 256 + threadIdx.x + gidOff;
    const int lane = gid & 31;
    const int fk = (gid >> 5) & 31;
    const int fm = gid >> 10;

    const int g = lane >> 2;
    const int k0 = fk * 16 + (lane & 3) * 2;
    const int m0 = fm * 16 + g;
    const int bt = m0 >> 7;
    const int u0 = m0 & 127;
    const int b = bt >> 8;

    const float* erow = e + (size_t)bt * HH;
    const float* dr0 = dmat + (size_t)(b * 128 + u0) * HH;
    const float* dr1 = dr0 + 8 * HH;

    float2 e01 = *(const float2*)(erow + k0);
    float2 e89 = *(const float2*)(erow + k0 + 8);
    float2 d001 = *(const float2*)(dr0 + k0);
    float2 d089 = *(const float2*)(dr0 + k0 + 8);
    float2 d101 = *(const float2*)(dr1 + k0);
    float2 d189 = *(const float2*)(dr1 + k0 + 8);

    float x0 = tanh_apx(e01.x + d001.x), x1 = tanh_apx(e01.y + d001.y);
    float x8 = tanh_apx(e89.x + d089.x), x9 = tanh_apx(e89.y + d089.y);
    float y0 = tanh_apx(e01.x + d101.x), y1 = tanh_apx(e01.y + d101.y);
    float y8 = tanh_apx(e89.x + d189.x), y9 = tanh_apx(e89.y + d189.y);

    Af[gid] = make_uint4(cvt_f16x2(x0, x1), cvt_f16x2(y0, y1),
                         cvt_f16x2(x8, x9), cvt_f16x2(y8, y9));
}

// ---------------- joint GEMM: out = A @ W^T + bias, single-pass HMMA ------
// CTA 128x128, 8 warps as 2(M) x 4(N); warp tile 64x32.
__global__ __launch_bounds__(256, 2) void joint_gemm(
    const uint4* __restrict__ Af, const uint2* __restrict__ Bf,
    const float* __restrict__ bias, float* __restrict__ out, int mtOff)
{
    const int tid = threadIdx.x;
    const int lane = tid & 31;
    const int wid = tid >> 5;
    const int wr = wid >> 2;            // 0..1  (64-row block)
    const int wc = wid & 3;             // 0..3  (32-col block)
    const int mt = blockIdx.y + mtOff;  // 0..1023
    const int nt = blockIdx.x;          // 0..7

    const int fmBase = mt * 8 + wr * 4;
    const int fnBase = nt * 16 + wc * 4;

    float c[4][4][4];
#pragma unroll
    for (int i = 0; i < 4; i++)
#pragma unroll
        for (int j = 0; j < 4; j++)
#pragma unroll
            for (int q = 0; q < 4; q++) c[i][j][q] = 0.f;

    const uint4* pa[4];
    const uint2* pb[4];
#pragma unroll
    for (int i = 0; i < 4; i++)
        pa[i] = Af + ((size_t)(fmBase + i) * 32) * 32 + lane;
#pragma unroll
    for (int j = 0; j < 4; j++)
        pb[j] = Bf + ((size_t)(fnBase + j) * 32) * 32 + lane;

    for (int fk = 0; fk < 32; fk++) {
        uint4 a[4];
        uint2 b[4];
#pragma unroll
        for (int i = 0; i < 4; i++) { a[i] = __ldg(pa[i]); pa[i] += 32; }
#pragma unroll
        for (int j = 0; j < 4; j++) { b[j] = __ldg(pb[j]); pb[j] += 32; }
#pragma unroll
        for (int i = 0; i < 4; i++)
#pragma unroll
            for (int j = 0; j < 4; j++)
                mma16816(c[i][j], (const uint32_t*)&a[i], (const uint32_t*)&b[j]);
    }

    // epilogue: C frag lane mapping: rows g, g+8 ; cols 2t, 2t+1
    const int g = lane >> 2;
    const int t2 = (lane & 3) * 2;
#pragma unroll
    for (int j = 0; j < 4; j++) {
        const int col = nt * 128 + wc * 32 + j * 8 + t2;
        const float2 bv = *(const float2*)(bias + col);
#pragma unroll
        for (int i = 0; i < 4; i++) {
            const int row = mt * 128 + wr * 64 + i * 16 + g;
            float2 o0 = make_float2(c[i][j][0] + bv.x, c[i][j][1] + bv.y);
            float2 o1 = make_float2(c[i][j][2] + bv.x, c[i][j][3] + bv.y);
            *(float2*)(out + (size_t)row * VV + col) = o0;
            *(float2*)(out + (size_t)(row + 8) * VV + col) = o1;
        }
    }
}

// ---------------- launch (two-stream fork/join, graph-capturable) ----------
extern "C" void kernel_launch(void* const* d_in, const int* in_sizes, int n_in,
                              void* d_out, int out_size)
{
    const float* enc     = (const float*)d_in[0];
    const float* dec     = (const float*)d_in[1];
    const float* W_enc   = (const float*)d_in[2];
    const float* b_enc   = (const float*)d_in[3];
    const float* W_dec   = (const float*)d_in[4];
    const float* b_dec   = (const float*)d_in[5];
    const float* W_joint = (const float*)d_in[6];
    const float* b_joint = (const float*)d_in[7];
    float* out = (float*)d_out;

    float *e_ptr, *d_ptr;
    uint4 *af;
    uint2 *bf;
    cudaGetSymbolAddress((void**)&e_ptr, g_e);
    cudaGetSymbolAddress((void**)&d_ptr, g_d);
    cudaGetSymbolAddress((void**)&af, g_Af);
    cudaGetSymbolAddress((void**)&bf, g_Bf);

    static cudaStream_t s2 = nullptr;
    static cudaEvent_t evF = nullptr, evD = nullptr, evE = nullptr;
    static cudaEvent_t evP1 = nullptr, evP2 = nullptr, evP3 = nullptr;
    if (s2 == nullptr) {
        cudaStreamCreateWithFlags(&s2, cudaStreamNonBlocking);
        cudaEventCreateWithFlags(&evF, cudaEventDisableTiming);
        cudaEventCreateWithFlags(&evD, cudaEventDisableTiming);
        cudaEventCreateWithFlags(&evE, cudaEventDisableTiming);
        cudaEventCreateWithFlags(&evP1, cudaEventDisableTiming);
        cudaEventCreateWithFlags(&evP2, cudaEventDisableTiming);
        cudaEventCreateWithFlags(&evP3, cudaEventDisableTiming);
    }

    const int Q_GID = (MM / 16) * (HH / 16) * 32 / 4;  // 2097152 per quarter
    const int Q_MT = MM / 128 / 4;                     // 256 m-tiles per quarter

    // fork: s2 branches off the capture stream
    cudaEventRecord(evF, 0);
    cudaStreamWaitEvent(s2, evF, 0);

    // s2: pack_b ; proj_d -> evD
    pack_b<<<(VV / 8) * (HH / 16) * 32 / 256, 256, 0, s2>>>(W_joint, bf);
    sgemm_bias<<<dim3(4, 4), 256, 0, s2>>>(dec, W_dec, b_dec, d_ptr,
                                           BB * UU, HH, HH);
    cudaEventRecord(evD, s2);

    // s0: proj_e -> evE
    sgemm_bias<<<dim3(4, 8), 256>>>(enc, W_enc, b_enc, e_ptr, BB * TT, HH, HH);
    cudaEventRecord(evE, 0);

    // s2: pack quarters 1..3 (needs e; d already in-stream)
    cudaStreamWaitEvent(s2, evE, 0);
    pack_a<<<Q_GID / 256, 256, 0, s2>>>(e_ptr, d_ptr, af, 1 * Q_GID);
    cudaEventRecord(evP1, s2);
    pack_a<<<Q_GID / 256, 256, 0, s2>>>(e_ptr, d_ptr, af, 2 * Q_GID);
    cudaEventRecord(evP2, s2);
    pack_a<<<Q_GID / 256, 256, 0, s2>>>(e_ptr, d_ptr, af, 3 * Q_GID);
    cudaEventRecord(evP3, s2);

    // s0: pack quarter 0 (needs d), then the four gemm quarters
    cudaStreamWaitEvent(0, evD, 0);
    pack_a<<<Q_GID / 256, 256>>>(e_ptr, d_ptr, af, 0);
    joint_gemm<<<dim3(VV / 128, Q_MT), 256>>>(af, bf, b_joint, out, 0);
    cudaStreamWaitEvent(0, evP1, 0);
    joint_gemm<<<dim3(VV / 128, Q_MT), 256>>>(af, bf, b_joint, out, 1 * Q_MT);
    cudaStreamWaitEvent(0, evP2, 0);
    joint_gemm<<<dim3(VV / 128, Q_MT), 256>>>(af, bf, b_joint, out, 2 * Q_MT);
    cudaStreamWaitEvent(0, evP3, 0);
    joint_gemm<<<dim3(VV / 128, Q_MT), 256>>>(af, bf, b_joint, out, 3 * Q_MT);
    // join: waiting on evP3 above already covers the s2 branch
}